// round 4
// baseline (speedup 1.0000x reference)
#include <cuda_runtime.h>
#include <cuda_bf16.h>
#include <math.h>
#include <cstdint>

// ---------------- problem constants ----------------
#define BN_ 16384
#define D_IN 1024
#define H1 512
#define H2 256
#define H3 128
#define FH 64
#define NDOM 4
#define EMB 16
#define BMROWS 128
#define BP 16896            // padded row count, 132 tiles of 128

typedef __nv_bfloat16 bf16;

// ---------------- scratch (device globals) ----------------
__device__ bf16  g_norm[(size_t)BP * D_IN];
__device__ bf16  g_h1c[(size_t)BP * H1];
__device__ bf16  g_h1d[(size_t)BP * H1];
__device__ bf16  g_h2c[(size_t)BP * H2];
__device__ bf16  g_h2d[(size_t)BP * H2];
__device__ float g_h3c[(size_t)BP * H3];
__device__ float g_h3d[(size_t)BP * H3];
// transposed bf16 weights, [N,K] (K-major rows)
__device__ bf16  g_wc1[(size_t)H1 * D_IN];
__device__ bf16  g_wd1[(size_t)NDOM * H1 * D_IN];
__device__ bf16  g_wc2[(size_t)H2 * H1];
__device__ bf16  g_wd2[(size_t)NDOM * H2 * H1];
__device__ bf16  g_wc3[(size_t)H3 * H2];
__device__ bf16  g_wd3[(size_t)NDOM * H3 * H2];
__device__ int   g_perm[BP];
__device__ int   g_pdom[BP];
__device__ int   g_cnt[NDOM];
__device__ int   g_off[NDOM];
__device__ int   g_cur[NDOM];
__device__ float g_aux[NDOM];

// ---------------- PTX helpers ----------------
__device__ __forceinline__ uint32_t smem_u32(const void* p) {
    uint32_t a;
    asm("{ .reg .u64 t; cvta.to.shared.u64 t, %1; cvt.u32.u64 %0, t; }" : "=r"(a) : "l"(p));
    return a;
}

__device__ __forceinline__ void cp_async16(uint32_t dst, const void* src) {
    asm volatile("cp.async.ca.shared.global [%0], [%1], 16;"
                 :: "r"(dst), "l"(src) : "memory");
}
__device__ __forceinline__ void cp_commit() {
    asm volatile("cp.async.commit_group;" ::: "memory");
}
template <int N>
__device__ __forceinline__ void cp_wait() {
    asm volatile("cp.async.wait_group %0;" :: "n"(N) : "memory");
}

__device__ __forceinline__ void ldm_x4(uint32_t* r, uint32_t addr) {
    asm volatile("ldmatrix.sync.aligned.m8n8.x4.shared.b16 {%0,%1,%2,%3}, [%4];"
                 : "=r"(r[0]), "=r"(r[1]), "=r"(r[2]), "=r"(r[3]) : "r"(addr));
}

__device__ __forceinline__ void mma_bf16(float* d, const uint32_t* a, const uint32_t* b) {
    asm volatile(
        "mma.sync.aligned.m16n8k16.row.col.f32.bf16.bf16.f32 "
        "{%0,%1,%2,%3}, {%4,%5,%6,%7}, {%8,%9}, {%0,%1,%2,%3};"
        : "+f"(d[0]), "+f"(d[1]), "+f"(d[2]), "+f"(d[3])
        : "r"(a[0]), "r"(a[1]), "r"(a[2]), "r"(a[3]), "r"(b[0]), "r"(b[1]));
}

// ---------------- sort infrastructure ----------------
__global__ void reset_kernel() {
    int i = blockIdx.x * blockDim.x + threadIdx.x;
    if (i < BP) { g_perm[i] = -1; g_pdom[i] = 0; }
    if (i < NDOM) g_cnt[i] = 0;
}

__global__ void count_kernel(const int* __restrict__ dids) {
    __shared__ int sc[NDOM];
    int tid = threadIdx.x;
    if (tid < NDOM) sc[tid] = 0;
    __syncthreads();
    int i = blockIdx.x * blockDim.x + tid;
    if (i < BN_) atomicAdd(&sc[dids[i]], 1);
    __syncthreads();
    if (tid < NDOM && sc[tid]) atomicAdd(&g_cnt[tid], sc[tid]);
}

__global__ void offset_kernel() {
    if (threadIdx.x == 0) {
        int off = 0;
        for (int d = 0; d < NDOM; d++) {
            g_off[d] = off; g_cur[d] = off;
            off += (g_cnt[d] + BMROWS - 1) & ~(BMROWS - 1);
        }
    }
}

__global__ void scatter_kernel(const int* __restrict__ dids) {
    __shared__ int sc[NDOM], sbase[NDOM];
    int tid = threadIdx.x;
    if (tid < NDOM) sc[tid] = 0;
    __syncthreads();
    int i = blockIdx.x * blockDim.x + tid;
    int d = -1, rank = 0;
    if (i < BN_) {
        d = dids[i];
        rank = atomicAdd(&sc[d], 1);
    }
    __syncthreads();
    if (tid < NDOM && sc[tid]) sbase[tid] = atomicAdd(&g_cur[tid], sc[tid]);
    __syncthreads();
    if (d >= 0) g_perm[sbase[d] + rank] = i;
}

__global__ void pdom_kernel() {
    int p = blockIdx.x * blockDim.x + threadIdx.x;
    if (p < BP) {
        int dm = 0;
        #pragma unroll
        for (int d = 0; d < NDOM; d++) {
            int s = g_off[d];
            int e = s + ((g_cnt[d] + BMROWS - 1) & ~(BMROWS - 1));
            if (p >= s && p < e) dm = d;
        }
        g_pdom[p] = dm;
    }
}

// aux net (domain-only) -> 4 scalars
__global__ void aux_kernel(const float* __restrict__ dom_emb,
                           const float* __restrict__ aW1, const float* __restrict__ ab1,
                           const float* __restrict__ aW2, const float* __restrict__ ab2) {
    int w = threadIdx.x >> 5;
    int j = threadIdx.x & 31;
    float s = ab1[j];
    #pragma unroll
    for (int i = 0; i < EMB; i++) s += dom_emb[w * EMB + i] * aW1[i * 32 + j];
    float v = fmaxf(s, 0.f) * aW2[j];
    #pragma unroll
    for (int o = 16; o; o >>= 1) v += __shfl_xor_sync(0xFFFFFFFFu, v, o);
    if (j == 0) g_aux[w] = v + ab2[0];
}

// ---------------- weight transpose + convert: W[K,N] f32 -> Wt[N,K] bf16 ----------------
// DST: 0..5 selects which device-global to write
template <int DST>
__global__ __launch_bounds__(256) void wt_kernel(const float* __restrict__ W, int K, int N) {
    bf16* Wt;
    if constexpr (DST == 0) Wt = g_wc1;
    if constexpr (DST == 1) Wt = g_wd1;
    if constexpr (DST == 2) Wt = g_wc2;
    if constexpr (DST == 3) Wt = g_wd2;
    if constexpr (DST == 4) Wt = g_wc3;
    if constexpr (DST == 5) Wt = g_wd3;
    __shared__ float t[32][33];
    int n0 = blockIdx.x * 32, k0 = blockIdx.y * 32;
    size_t bo = (size_t)blockIdx.z * K * N;
    int tx = threadIdx.x & 31, ty = threadIdx.x >> 5;  // 32x8
    #pragma unroll
    for (int i = ty; i < 32; i += 8)
        t[i][tx] = W[bo + (size_t)(k0 + i) * N + n0 + tx];
    __syncthreads();
    #pragma unroll
    for (int i = ty; i < 32; i += 8)
        Wt[bo + (size_t)(n0 + i) * K + k0 + tx] = __float2bfloat16(t[tx][i]);
}

// ---------------- layernorm + domain affine -> bf16 permuted ----------------
__global__ __launch_bounds__(256) void ln_kernel(const float* __restrict__ x,
                                                 const int* __restrict__ dids,
                                                 const float* __restrict__ pnw,
                                                 const float* __restrict__ pnb) {
    int p = blockIdx.x;
    int tid = threadIdx.x;
    bf16* out = g_norm + (size_t)p * D_IN;
    int r = g_perm[p];
    if (r < 0) {
        uint2 z = {0u, 0u};
        *(uint2*)&out[tid * 4] = z;
        return;
    }
    const float* xr = x + (size_t)r * D_IN;
    float4 v = *(const float4*)&xr[tid * 4];
    float s = v.x + v.y + v.z + v.w;
    float q = v.x * v.x + v.y * v.y + v.z * v.z + v.w * v.w;
    #pragma unroll
    for (int o = 16; o; o >>= 1) {
        s += __shfl_xor_sync(0xFFFFFFFFu, s, o);
        q += __shfl_xor_sync(0xFFFFFFFFu, q, o);
    }
    __shared__ float ss[8], sq[8];
    __shared__ float smean, sinv;
    if ((tid & 31) == 0) { ss[tid >> 5] = s; sq[tid >> 5] = q; }
    __syncthreads();
    if (tid < 32) {
        s = (tid < 8) ? ss[tid] : 0.f;
        q = (tid < 8) ? sq[tid] : 0.f;
        #pragma unroll
        for (int o = 4; o; o >>= 1) {
            s += __shfl_xor_sync(0xFFFFFFFFu, s, o);
            q += __shfl_xor_sync(0xFFFFFFFFu, q, o);
        }
        if (tid == 0) {
            float mean = s * (1.f / D_IN);
            float var = q * (1.f / D_IN) - mean * mean;
            smean = mean;
            sinv = rsqrtf(var + 1e-5f);
        }
    }
    __syncthreads();
    int d = dids[r];
    float4 w = *(const float4*)&pnw[(size_t)d * D_IN + tid * 4];
    float4 b = *(const float4*)&pnb[(size_t)d * D_IN + tid * 4];
    float m = smean, inv = sinv;
    bf16 o[4];
    o[0] = __float2bfloat16((v.x - m) * inv * w.x + b.x);
    o[1] = __float2bfloat16((v.y - m) * inv * w.y + b.y);
    o[2] = __float2bfloat16((v.z - m) * inv * w.z + b.z);
    o[3] = __float2bfloat16((v.w - m) * inv * w.w + b.w);
    *(uint2*)&out[tid * 4] = *(uint2*)o;
}

// ---------------- HMMA GEMM: C[128xN tile] = A[128xK] * W[N,K]^T + bias ----------------
// CTA 128x128, BK=32, 8 warps (4 along M x 2 along N), warp tile 32x64.
// smem: padded rows of 40 bf16 (80B) -> conflict-free ldmatrix + cp.async stores.
#define KPAD 40
#define STAGE_BYTES (128 * KPAD * 2)   // 10240

template <int K, int N, int LAYER, bool RELU, bool OUTF32>
__global__ __launch_bounds__(256) void gemm_hmma(const bf16* __restrict__ Wc,
                                                 const bf16* __restrict__ Wd,
                                                 const float* __restrict__ bc,
                                                 const float* __restrict__ bd) {
    __shared__ bf16 As[2][128 * KPAD];
    __shared__ bf16 Bs[2][128 * KPAD];

    const int tid = threadIdx.x;
    const int wid = tid >> 5, lane = tid & 31;
    const int warpM = wid & 3, warpN = wid >> 2;
    const int m0 = blockIdx.y * 128;
    const int n0 = blockIdx.x * 128;
    const int z = blockIdx.z;

    const bf16* A; void* C;
    if constexpr (LAYER == 1) { A = g_norm;              C = z ? (void*)g_h1d : (void*)g_h1c; }
    if constexpr (LAYER == 2) { A = z ? g_h1d : g_h1c;   C = z ? (void*)g_h2d : (void*)g_h2c; }
    if constexpr (LAYER == 3) { A = z ? g_h2d : g_h2c;   C = z ? (void*)g_h3d : (void*)g_h3c; }

    const bf16* W; const float* bias;
    if (z == 0) { W = Wc; bias = bc; }
    else {
        int dom = g_pdom[m0];
        W = Wd + (size_t)dom * K * N;
        bias = bd + (size_t)dom * N;
    }

    const uint32_t sA = smem_u32(As);
    const uint32_t sB = smem_u32(Bs);

    // per-thread cp.async chunk coords: 512 16B-chunks per tile, 2 per thread
    const int r0 = tid >> 1;              // rows 0..127 (chunk pair per row-half)
    // chunk id layout: id = t and t+256 -> row = id>>2, ch = id&3
    const int rowA0 = tid >> 2, chA0 = tid & 3;
    const int rowA1 = (tid + 256) >> 2, chA1 = tid & 3;
    (void)r0;

    constexpr int NIT = K / 32;

    auto load_stage = [&](int s, int i) {
        const int k0 = i * 32;
        {
            const char* src = (const char*)(A + (size_t)(m0 + rowA0) * K + k0 + chA0 * 8);
            cp_async16(sA + s * STAGE_BYTES + rowA0 * (KPAD * 2) + chA0 * 16, src);
            const char* src1 = (const char*)(A + (size_t)(m0 + rowA1) * K + k0 + chA1 * 8);
            cp_async16(sA + s * STAGE_BYTES + rowA1 * (KPAD * 2) + chA1 * 16, src1);
            const char* srcB = (const char*)(W + (size_t)(n0 + rowA0) * K + k0 + chA0 * 8);
            cp_async16(sB + s * STAGE_BYTES + rowA0 * (KPAD * 2) + chA0 * 16, srcB);
            const char* srcB1 = (const char*)(W + (size_t)(n0 + rowA1) * K + k0 + chA1 * 8);
            cp_async16(sB + s * STAGE_BYTES + rowA1 * (KPAD * 2) + chA1 * 16, srcB1);
        }
        cp_commit();
    };

    float acc[2][8][4];
    #pragma unroll
    for (int t = 0; t < 2; t++)
        #pragma unroll
        for (int n = 0; n < 8; n++)
            #pragma unroll
            for (int c = 0; c < 4; c++) acc[t][n][c] = 0.f;

    load_stage(0, 0);

    for (int i = 0; i < NIT; i++) {
        const int s = i & 1;
        if (i + 1 < NIT) {
            load_stage(s ^ 1, i + 1);
            cp_wait<1>();
        } else {
            cp_wait<0>();
        }
        __syncthreads();

        #pragma unroll
        for (int kk = 0; kk < 2; kk++) {
            uint32_t a[2][4];
            #pragma unroll
            for (int t = 0; t < 2; t++) {
                int row = warpM * 32 + t * 16 + (lane & 15);
                int colb = (lane >> 4) * 16 + kk * 32;
                ldm_x4(a[t], sA + s * STAGE_BYTES + row * (KPAD * 2) + colb);
            }
            uint32_t b[4][4];
            #pragma unroll
            for (int g = 0; g < 4; g++) {
                int row = warpN * 64 + g * 16 + (lane & 7) + ((lane >> 4) & 1) * 8;
                int colb = ((lane >> 3) & 1) * 16 + kk * 32;
                ldm_x4(b[g], sB + s * STAGE_BYTES + row * (KPAD * 2) + colb);
            }
            #pragma unroll
            for (int t = 0; t < 2; t++)
                #pragma unroll
                for (int g = 0; g < 4; g++) {
                    mma_bf16(acc[t][2 * g],     a[t], &b[g][0]);
                    mma_bf16(acc[t][2 * g + 1], a[t], &b[g][2]);
                }
        }
        __syncthreads();
    }

    // epilogue: bias + relu + store
    #pragma unroll
    for (int t = 0; t < 2; t++) {
        int mrow = m0 + warpM * 32 + t * 16 + (lane >> 2);
        #pragma unroll
        for (int n8 = 0; n8 < 8; n8++) {
            int ncol = n0 + warpN * 64 + n8 * 8 + (lane & 3) * 2;
            float b0 = __ldg(&bias[ncol]);
            float b1 = __ldg(&bias[ncol + 1]);
            float v0 = acc[t][n8][0] + b0;
            float v1 = acc[t][n8][1] + b1;
            float v2 = acc[t][n8][2] + b0;
            float v3 = acc[t][n8][3] + b1;
            if (RELU) {
                v0 = fmaxf(v0, 0.f); v1 = fmaxf(v1, 0.f);
                v2 = fmaxf(v2, 0.f); v3 = fmaxf(v3, 0.f);
            }
            if constexpr (OUTF32) {
                float* Cp = (float*)C;
                float2 p0 = {v0, v1}, p1 = {v2, v3};
                *(float2*)&Cp[(size_t)mrow * N + ncol] = p0;
                *(float2*)&Cp[(size_t)(mrow + 8) * N + ncol] = p1;
            } else {
                bf16* Cp = (bf16*)C;
                __nv_bfloat162 p0 = {__float2bfloat16(v0), __float2bfloat16(v1)};
                __nv_bfloat162 p1 = {__float2bfloat16(v2), __float2bfloat16(v3)};
                *(__nv_bfloat162*)&Cp[(size_t)mrow * N + ncol] = p0;
                *(__nv_bfloat162*)&Cp[(size_t)(mrow + 8) * N + ncol] = p1;
            }
        }
    }
}

// ---------------- fuse + final MLP + aux + sigmoid ----------------
__global__ __launch_bounds__(256) void final_kernel(const float* __restrict__ fW1,
                                                    const float* __restrict__ fb1,
                                                    const float* __restrict__ fW2,
                                                    const float* __restrict__ fb2,
                                                    float* __restrict__ out) {
    __shared__ float sW1[H3 * FH];
    __shared__ float sb1[FH], sW2[FH];
    __shared__ float sf[8][H3];

    int tid = threadIdx.x;
    for (int i = tid; i < H3 * FH; i += 256) sW1[i] = fW1[i];
    if (tid < FH) { sb1[tid] = fb1[tid]; sW2[tid] = fW2[tid]; }
    __syncthreads();

    int w = tid >> 5, lane = tid & 31;
    int p = blockIdx.x * 8 + w;
    int r = g_perm[p];

    #pragma unroll
    for (int q = 0; q < 4; q++) {
        int i = q * 32 + lane;
        float c = g_h3c[(size_t)p * H3 + i];
        float d = g_h3d[(size_t)p * H3 + i];
        sf[w][i] = c * tanhf(d);
    }
    __syncwarp();

    float acc = 0.f;
    #pragma unroll
    for (int jj = 0; jj < 2; jj++) {
        int j = jj * 32 + lane;
        float h = sb1[j];
        #pragma unroll 8
        for (int i = 0; i < H3; i++) h += sf[w][i] * sW1[i * FH + j];
        acc += fmaxf(h, 0.f) * sW2[j];
    }
    #pragma unroll
    for (int o = 16; o; o >>= 1) acc += __shfl_xor_sync(0xFFFFFFFFu, acc, o);

    if (lane == 0 && r >= 0) {
        float v = acc + fb2[0] + g_aux[g_pdom[p]];
        out[r] = 1.f / (1.f + expf(-v));
    }
}

// ---------------- launch ----------------
extern "C" void kernel_launch(void* const* d_in, const int* in_sizes, int n_in,
                              void* d_out, int out_size) {
    const float* x      = (const float*)d_in[0];
    const int*   dids   = (const int*)  d_in[1];
    const float* pnw    = (const float*)d_in[2];
    const float* pnb    = (const float*)d_in[3];
    const float* cW1    = (const float*)d_in[4];
    const float* cb1    = (const float*)d_in[5];
    const float* cW2    = (const float*)d_in[6];
    const float* cb2    = (const float*)d_in[7];
    const float* cW3    = (const float*)d_in[8];
    const float* cb3    = (const float*)d_in[9];
    const float* dW1    = (const float*)d_in[10];
    const float* db1    = (const float*)d_in[11];
    const float* dW2    = (const float*)d_in[12];
    const float* db2    = (const float*)d_in[13];
    const float* dW3    = (const float*)d_in[14];
    const float* db3    = (const float*)d_in[15];
    const float* fW1    = (const float*)d_in[16];
    const float* fb1    = (const float*)d_in[17];
    const float* fW2    = (const float*)d_in[18];
    const float* fb2    = (const float*)d_in[19];
    const float* dom_emb= (const float*)d_in[20];
    const float* aW1    = (const float*)d_in[21];
    const float* ab1    = (const float*)d_in[22];
    const float* aW2    = (const float*)d_in[23];
    const float* ab2    = (const float*)d_in[24];
    float* out = (float*)d_out;

    // sort + aux
    reset_kernel<<<(BP + 255) / 256, 256>>>();
    count_kernel<<<(BN_ + 255) / 256, 256>>>(dids);
    offset_kernel<<<1, 32>>>();
    scatter_kernel<<<(BN_ + 255) / 256, 256>>>(dids);
    pdom_kernel<<<(BP + 255) / 256, 256>>>();
    aux_kernel<<<1, 128>>>(dom_emb, aW1, ab1, aW2, ab2);

    // weight transpose + bf16 convert
    wt_kernel<0><<<dim3(H1 / 32, D_IN / 32, 1),    256>>>(cW1, D_IN, H1);
    wt_kernel<1><<<dim3(H1 / 32, D_IN / 32, NDOM), 256>>>(dW1, D_IN, H1);
    wt_kernel<2><<<dim3(H2 / 32, H1 / 32, 1),      256>>>(cW2, H1, H2);
    wt_kernel<3><<<dim3(H2 / 32, H1 / 32, NDOM),   256>>>(dW2, H1, H2);
    wt_kernel<4><<<dim3(H3 / 32, H2 / 32, 1),      256>>>(cW3, H2, H3);
    wt_kernel<5><<<dim3(H3 / 32, H2 / 32, NDOM),   256>>>(dW3, H2, H3);

    // layernorm -> bf16 permuted activations
    ln_kernel<<<BP, 256>>>(x, dids, pnw, pnb);

    // HMMA GEMMs (z: 0=center, 1=domain)
    gemm_hmma<D_IN, H1, 1, true,  false>
        <<<dim3(H1 / 128, BP / 128, 2), 256>>>(g_wc1, g_wd1, cb1, db1);
    gemm_hmma<H1,   H2, 2, true,  false>
        <<<dim3(H2 / 128, BP / 128, 2), 256>>>(g_wc2, g_wd2, cb2, db2);
    gemm_hmma<H2,   H3, 3, false, true>
        <<<dim3(H3 / 128, BP / 128, 2), 256>>>(g_wc3, g_wd3, cb3, db3);

    final_kernel<<<BP / 8, 256>>>(fW1, fb1, fW2, fb2, out);
}

// round 5
// speedup vs baseline: 2.4326x; 2.4326x over previous
#include <cuda_runtime.h>
#include <math.h>
#include <cstdint>

// ---------------- problem constants ----------------
#define BN_ 16384
#define D_IN 1024
#define H1 512
#define H2 256
#define H3 128
#define FH 64
#define NDOM 4
#define EMB 16
#define BMROWS 128
#define BP 16896            // 132 tiles of 128 (>= 16384 + max padding 508)
#define NCB 64              // count blocks

// ---------------- scratch (device globals) ----------------
__device__ float g_norm[(size_t)BP * D_IN];
__device__ float g_h1c[(size_t)BP * H1];
__device__ float g_h1d[(size_t)BP * H1];
__device__ float g_h2c[(size_t)BP * H2];
__device__ float g_h2d[(size_t)BP * H2];
__device__ float g_h3c[(size_t)BP * H3];
__device__ float g_h3d[(size_t)BP * H3];
__device__ int   g_perm[BP];
__device__ int   g_bcnt[NCB][NDOM];
__device__ int   g_cnt[NDOM];
__device__ int   g_off[NDOM];
__device__ float g_aux[NDOM];

typedef unsigned long long u64;

// ---------------- f32x2 helpers ----------------
__device__ __forceinline__ u64 pack2(float x) {
    u64 r;
    asm("mov.b64 %0, {%1, %1};" : "=l"(r) : "r"(__float_as_uint(x)));
    return r;
}
__device__ __forceinline__ void fma2(u64& d, u64 a, u64 b) {
    asm("fma.rn.f32x2 %0, %1, %2, %0;" : "+l"(d) : "l"(a), "l"(b));
}
__device__ __forceinline__ float2 unpack2(u64 v) {
    uint32_t lo, hi;
    asm("mov.b64 {%0, %1}, %2;" : "=r"(lo), "=r"(hi) : "l"(v));
    float2 f;
    f.x = __uint_as_float(lo);
    f.y = __uint_as_float(hi);
    return f;
}

// pad region helpers
__device__ __forceinline__ int pad4(int c) { return (c + BMROWS - 1) & ~(BMROWS - 1); }

__device__ __forceinline__ int dom_of(int p) {
    int d = 0;
    #pragma unroll
    for (int k = 1; k < NDOM; k++) d += (p >= g_off[k]);
    return d;
}

// ---------------- sort: count (per-block partials, no global init needed) ----------------
__global__ __launch_bounds__(256) void count_kernel(const int* __restrict__ dids) {
    __shared__ int sc[NDOM];
    int tid = threadIdx.x;
    if (tid < NDOM) sc[tid] = 0;
    __syncthreads();
    int i = blockIdx.x * 256 + tid;
    atomicAdd(&sc[dids[i]], 1);
    __syncthreads();
    if (tid < NDOM) g_bcnt[blockIdx.x][tid] = sc[tid];
}

// ---------------- sort: scatter with inline prefix (also publishes off/cnt) ----------------
__global__ __launch_bounds__(256) void scatter_kernel(const int* __restrict__ dids) {
    __shared__ int pre[NDOM];   // this block's base slot per domain
    __shared__ int loc[NDOM];
    __shared__ int stot[NDOM], sbase[NDOM];
    int tid = threadIdx.x;
    if (tid < NDOM) {
        int d = tid, base = 0, tot = 0;
        #pragma unroll 8
        for (int b = 0; b < NCB; b++) {
            int c = g_bcnt[b][d];
            if (b < (int)blockIdx.x) base += c;
            tot += c;
        }
        stot[d] = tot; sbase[d] = base;
        loc[d] = 0;
    }
    __syncthreads();
    if (tid == 0) {
        int off = 0;
        #pragma unroll
        for (int d = 0; d < NDOM; d++) {
            pre[d] = off + sbase[d];
            if (blockIdx.x == 0) { g_off[d] = off; g_cnt[d] = stot[d]; }
            off += pad4(stot[d]);
        }
    }
    __syncthreads();
    int i = blockIdx.x * 256 + tid;
    int d = dids[i];
    int rank = atomicAdd(&loc[d], 1);
    g_perm[pre[d] + rank] = i;
}

// aux net (domain-only) -> 4 scalars
__global__ void aux_kernel(const float* __restrict__ dom_emb,
                           const float* __restrict__ aW1, const float* __restrict__ ab1,
                           const float* __restrict__ aW2, const float* __restrict__ ab2) {
    int w = threadIdx.x >> 5;
    int j = threadIdx.x & 31;
    float s = ab1[j];
    #pragma unroll
    for (int i = 0; i < EMB; i++) s += dom_emb[w * EMB + i] * aW1[i * 32 + j];
    float v = fmaxf(s, 0.f) * aW2[j];
    #pragma unroll
    for (int o = 16; o; o >>= 1) v += __shfl_xor_sync(0xFFFFFFFFu, v, o);
    if (j == 0) g_aux[w] = v + ab2[0];
}

// ---------------- layernorm + domain affine, permuted order ----------------
__global__ __launch_bounds__(256) void ln_kernel(const float* __restrict__ x,
                                                 const int* __restrict__ dids,
                                                 const float* __restrict__ pnw,
                                                 const float* __restrict__ pnb) {
    int p = blockIdx.x;
    int tid = threadIdx.x;
    float* out = g_norm + (size_t)p * D_IN;
    int d0 = dom_of(p);
    bool pad = (p - g_off[d0]) >= g_cnt[d0];
    if (pad) {
        float4 z = {0.f, 0.f, 0.f, 0.f};
        *(float4*)&out[tid * 4] = z;
        return;
    }
    int r = g_perm[p];
    const float* xr = x + (size_t)r * D_IN;
    float4 v = *(const float4*)&xr[tid * 4];
    float s = v.x + v.y + v.z + v.w;
    float q = v.x * v.x + v.y * v.y + v.z * v.z + v.w * v.w;
    #pragma unroll
    for (int o = 16; o; o >>= 1) {
        s += __shfl_xor_sync(0xFFFFFFFFu, s, o);
        q += __shfl_xor_sync(0xFFFFFFFFu, q, o);
    }
    __shared__ float ss[8], sq[8];
    __shared__ float smean, sinv;
    if ((tid & 31) == 0) { ss[tid >> 5] = s; sq[tid >> 5] = q; }
    __syncthreads();
    if (tid < 32) {
        s = (tid < 8) ? ss[tid] : 0.f;
        q = (tid < 8) ? sq[tid] : 0.f;
        #pragma unroll
        for (int o = 4; o; o >>= 1) {
            s += __shfl_xor_sync(0xFFFFFFFFu, s, o);
            q += __shfl_xor_sync(0xFFFFFFFFu, q, o);
        }
        if (tid == 0) {
            float mean = s * (1.f / D_IN);
            float var = q * (1.f / D_IN) - mean * mean;
            smean = mean;
            sinv = rsqrtf(var + 1e-5f);
        }
    }
    __syncthreads();
    int d = dids[r];
    float4 w = *(const float4*)&pnw[(size_t)d * D_IN + tid * 4];
    float4 b = *(const float4*)&pnb[(size_t)d * D_IN + tid * 4];
    float m = smean, inv = sinv;
    float4 o;
    o.x = (v.x - m) * inv * w.x + b.x;
    o.y = (v.y - m) * inv * w.y + b.y;
    o.z = (v.z - m) * inv * w.z + b.z;
    o.w = (v.w - m) * inv * w.w + b.w;
    *(float4*)&out[tid * 4] = o;
}

// ---------------- tiled GEMM: 128x128x16, 256 threads, 8x8 per thread, f32x2 math ----
// grid.z = 0 -> center path, 1 -> domain path
template <int K, int N, bool RELU, int LAYER>
__global__ __launch_bounds__(256, 2) void gemm_kernel(const float* __restrict__ Wc,
                                                      const float* __restrict__ Wd,
                                                      const float* __restrict__ bc,
                                                      const float* __restrict__ bd) {
    constexpr int BM = 128, BNT = 128, BK = 16;
    __shared__ float As[BK][BM];
    __shared__ float Bs[BK][BNT];

    const int tid = threadIdx.x;
    const int tx = tid & 15, ty = tid >> 4;
    const int by = blockIdx.y, bx = blockIdx.x;
    const int z = blockIdx.z;
    const int m0 = by * BM;
    const int n0 = bx * BNT;

    const float* A; float* C;
    if constexpr (LAYER == 1) { A = g_norm;               C = z ? g_h1d : g_h1c; }
    if constexpr (LAYER == 2) { A = z ? g_h1d : g_h1c;    C = z ? g_h2d : g_h2c; }
    if constexpr (LAYER == 3) { A = z ? g_h2d : g_h2c;    C = z ? g_h3d : g_h3c; }

    const float* W; const float* bias;
    if (z == 0) { W = Wc; bias = bc; }
    else {
        int dom = dom_of(m0);
        W = Wd + (size_t)dom * K * N;
        bias = bd + (size_t)dom * N;
    }

    // 8x8 accumulators as 32 f32x2 pairs: acc[i][j] covers rows (i), col-pairs:
    // j=0 -> (tx*4+0, +1), j=1 -> (+2, +3), j=2 -> (+64, +65), j=3 -> (+66, +67)
    u64 acc[8][4];
    #pragma unroll
    for (int i = 0; i < 8; i++)
        #pragma unroll
        for (int j = 0; j < 4; j++) acc[i][j] = 0ull;

    for (int k0 = 0; k0 < K; k0 += BK) {
        #pragma unroll
        for (int e = 0; e < 2; e++) {
            int lin = tid + e * 256;
            int arow = lin >> 2, ac = (lin & 3) * 4;
            float4 v = *(const float4*)&A[(size_t)(m0 + arow) * K + k0 + ac];
            As[ac + 0][arow] = v.x;
            As[ac + 1][arow] = v.y;
            As[ac + 2][arow] = v.z;
            As[ac + 3][arow] = v.w;
            int bk = lin >> 5, bn = (lin & 31) * 4;
            *(float4*)&Bs[bk][bn] = *(const float4*)&W[(size_t)(k0 + bk) * N + n0 + bn];
        }
        __syncthreads();
        #pragma unroll
        for (int kk = 0; kk < BK; kk++) {
            float a[8];
            *(float4*)&a[0] = *(const float4*)&As[kk][ty * 4];
            *(float4*)&a[4] = *(const float4*)&As[kk][ty * 4 + 64];
            const u64* bp0 = (const u64*)&Bs[kk][tx * 4];
            const u64* bp1 = (const u64*)&Bs[kk][tx * 4 + 64];
            u64 b0 = bp0[0], b1 = bp0[1], b2 = bp1[0], b3 = bp1[1];
            #pragma unroll
            for (int i = 0; i < 8; i++) {
                u64 ai = pack2(a[i]);
                fma2(acc[i][0], ai, b0);
                fma2(acc[i][1], ai, b1);
                fma2(acc[i][2], ai, b2);
                fma2(acc[i][3], ai, b3);
            }
        }
        __syncthreads();
    }

    float bj[8];
    #pragma unroll
    for (int j = 0; j < 8; j++) {
        int cn = tx * 4 + (j & 3) + ((j >> 2) * 64);
        bj[j] = bias[n0 + cn];
    }
    #pragma unroll
    for (int i = 0; i < 8; i++) {
        int m = m0 + ty * 4 + (i & 3) + ((i >> 2) * 64);
        float2 c0 = unpack2(acc[i][0]);
        float2 c1 = unpack2(acc[i][1]);
        float2 c2 = unpack2(acc[i][2]);
        float2 c3 = unpack2(acc[i][3]);
        float4 o0, o1;
        o0.x = c0.x + bj[0]; o0.y = c0.y + bj[1];
        o0.z = c1.x + bj[2]; o0.w = c1.y + bj[3];
        o1.x = c2.x + bj[4]; o1.y = c2.y + bj[5];
        o1.z = c3.x + bj[6]; o1.w = c3.y + bj[7];
        if (RELU) {
            o0.x = fmaxf(o0.x, 0.f); o0.y = fmaxf(o0.y, 0.f);
            o0.z = fmaxf(o0.z, 0.f); o0.w = fmaxf(o0.w, 0.f);
            o1.x = fmaxf(o1.x, 0.f); o1.y = fmaxf(o1.y, 0.f);
            o1.z = fmaxf(o1.z, 0.f); o1.w = fmaxf(o1.w, 0.f);
        }
        *(float4*)&C[(size_t)m * N + n0 + tx * 4]      = o0;
        *(float4*)&C[(size_t)m * N + n0 + tx * 4 + 64] = o1;
    }
}

// ---------------- fuse + final MLP + aux + sigmoid (one warp per row) ----------------
__global__ __launch_bounds__(256) void final_kernel(const float* __restrict__ fW1,
                                                    const float* __restrict__ fb1,
                                                    const float* __restrict__ fW2,
                                                    const float* __restrict__ fb2,
                                                    float* __restrict__ out) {
    __shared__ float sW1[H3 * FH];   // 32KB
    __shared__ float sb1[FH], sW2[FH];
    __shared__ float sf[8][H3];

    int tid = threadIdx.x;
    for (int i = tid; i < H3 * FH; i += 256) sW1[i] = fW1[i];
    if (tid < FH) { sb1[tid] = fb1[tid]; sW2[tid] = fW2[tid]; }
    __syncthreads();

    int w = tid >> 5, lane = tid & 31;
    int p = blockIdx.x * 8 + w;
    int d0 = dom_of(p);
    bool pad = (p - g_off[d0]) >= g_cnt[d0];

    #pragma unroll
    for (int q = 0; q < 4; q++) {
        int i = q * 32 + lane;
        float c = g_h3c[(size_t)p * H3 + i];
        float d = g_h3d[(size_t)p * H3 + i];
        sf[w][i] = c * tanhf(d);
    }
    __syncwarp();

    float acc = 0.f;
    #pragma unroll
    for (int jj = 0; jj < 2; jj++) {
        int j = jj * 32 + lane;
        float h = sb1[j];
        #pragma unroll 8
        for (int i = 0; i < H3; i++) h += sf[w][i] * sW1[i * FH + j];
        acc += fmaxf(h, 0.f) * sW2[j];
    }
    #pragma unroll
    for (int o = 16; o; o >>= 1) acc += __shfl_xor_sync(0xFFFFFFFFu, acc, o);

    if (lane == 0 && !pad) {
        int r = g_perm[p];
        float v = acc + fb2[0] + g_aux[d0];
        out[r] = 1.f / (1.f + expf(-v));
    }
}

// ---------------- launch ----------------
extern "C" void kernel_launch(void* const* d_in, const int* in_sizes, int n_in,
                              void* d_out, int out_size) {
    const float* x      = (const float*)d_in[0];
    const int*   dids   = (const int*)  d_in[1];
    const float* pnw    = (const float*)d_in[2];
    const float* pnb    = (const float*)d_in[3];
    const float* cW1    = (const float*)d_in[4];
    const float* cb1    = (const float*)d_in[5];
    const float* cW2    = (const float*)d_in[6];
    const float* cb2    = (const float*)d_in[7];
    const float* cW3    = (const float*)d_in[8];
    const float* cb3    = (const float*)d_in[9];
    const float* dW1    = (const float*)d_in[10];
    const float* db1    = (const float*)d_in[11];
    const float* dW2    = (const float*)d_in[12];
    const float* db2    = (const float*)d_in[13];
    const float* dW3    = (const float*)d_in[14];
    const float* db3    = (const float*)d_in[15];
    const float* fW1    = (const float*)d_in[16];
    const float* fb1    = (const float*)d_in[17];
    const float* fW2    = (const float*)d_in[18];
    const float* fb2    = (const float*)d_in[19];
    const float* dom_emb= (const float*)d_in[20];
    const float* aW1    = (const float*)d_in[21];
    const float* ab1    = (const float*)d_in[22];
    const float* aW2    = (const float*)d_in[23];
    const float* ab2    = (const float*)d_in[24];
    float* out = (float*)d_out;

    count_kernel<<<NCB, 256>>>(dids);                 // 0
    scatter_kernel<<<NCB, 256>>>(dids);               // 1 (also publishes off/cnt)
    ln_kernel<<<BP, 256>>>(x, dids, pnw, pnb);        // 2

    gemm_kernel<D_IN, H1, true,  1>                   // 3
        <<<dim3(H1 / 128, BP / 128, 2), 256>>>(cW1, dW1, cb1, db1);
    gemm_kernel<H1,   H2, true,  2>                   // 4
        <<<dim3(H2 / 128, BP / 128, 2), 256>>>(cW2, dW2, cb2, db2);
    gemm_kernel<H2,   H3, false, 3>                   // 5
        <<<dim3(H3 / 128, BP / 128, 2), 256>>>(cW3, dW3, cb3, db3);

    aux_kernel<<<1, 128>>>(dom_emb, aW1, ab1, aW2, ab2);   // 6
    final_kernel<<<BP / 8, 256>>>(fW1, fb1, fW2, fb2, out); // 7
}